// round 7
// baseline (speedup 1.0000x reference)
#include <cuda_runtime.h>
#include <cstdint>

typedef unsigned long long ull;

#define NTHREADS 512
#define TILE_B   32
#define TILE_N   512
#define KSTAGE   16          // floats per stage per anchor row (64B)
#define NKST     16          // 256/16 k-slots per chunk
#define RING     3
#define DFEAT    256
#define GRAPHK   50
#define BTOT     2048

// shared memory layout (floats)
#define SM_FS    0                                  // Fs [256][32] k-major
#define SM_AS    (DFEAT * TILE_B)                   // As ring [3][512][16]
#define SM_STG   (SM_AS + RING * TILE_N * KSTAGE)   // stg [32][512]
#define SM_VALS  (SM_STG + TILE_B * TILE_N)         // vals [32][52]
#define SM_LABS  (SM_VALS + TILE_B * 52)            // meta [32][52]
#define SM_TOTAL (SM_LABS + TILE_B * 52)
#define SMEM_BYTES (SM_TOTAL * 4)                   // ~210 KB

#define NEG_INF (-3.402823466e38f)
#define POS_INF ( 3.402823466e38f)
#define FULLMASK 0xffffffffu

__device__ float    g_svals[2][BTOT][GRAPHK];
__device__ unsigned g_smeta[2][BTOT][GRAPHK];

__device__ __forceinline__ ull ffma2(ull a, ull b, ull c) {
    ull d;
    asm("fma.rn.f32x2 %0, %1, %2, %3;" : "=l"(d) : "l"(a), "l"(b), "l"(c));
    return d;
}
__device__ __forceinline__ ull packdup(float x) {
    ull d;
    asm("mov.b64 %0, {%1, %1};" : "=l"(d) : "f"(x));
    return d;
}
__device__ __forceinline__ void cpasync16(uint32_t dst, const void* src, int srcbytes) {
    asm volatile("cp.async.cg.shared.global [%0], [%1], 16, %2;"
                 :: "r"(dst), "l"(src), "r"(srcbytes));
}
__device__ __forceinline__ void cp_commit() {
    asm volatile("cp.async.commit_group;" ::: "memory");
}
template <int N> __device__ __forceinline__ void cp_wait() {
    asm volatile("cp.async.wait_group %0;" :: "n"(N) : "memory");
}

__global__ __launch_bounds__(NTHREADS, 1)
void knn_sim_main(const float* __restrict__ features,
                  const float* __restrict__ anchor,
                  const int*   __restrict__ anchor_label,
                  int B, int N)
{
    extern __shared__ float sm[];
    float*    Fs   = sm + SM_FS;
    float*    As   = sm + SM_AS;
    float*    stg  = sm + SM_STG;
    float*    vals = sm + SM_VALS;
    unsigned* labs = (unsigned*)(sm + SM_LABS);

    uint32_t sm_base;
    asm("{ .reg .u64 t; cvta.to.shared.u64 t, %1; cvt.u32.u64 %0, t; }"
        : "=r"(sm_base) : "l"(sm));
    const uint32_t As_bytes = sm_base + SM_AS * 4;

    const int tx   = threadIdx.x;
    const int lane = tx & 31;
    const int warp = tx >> 5;                // 0..15
    const int half = blockIdx.x & 1;
    const int bt   = blockIdx.x >> 1;        // 0..63
    const int b0   = bt * TILE_B;

    const int Nh0     = (N + 1) >> 1;
    const int n_begin = half ? Nh0 : 0;
    const int n_end   = half ? N   : Nh0;
    const int Nh      = n_end - n_begin;

    // ---- features tile transposed: Fs[k][r] (r = 0..31) ----
    for (int m = 0; m < 16; m++) {
        int idx = tx + NTHREADS * m;         // 0..8191
        int r = idx >> 8;                    // 0..31
        int k = idx & 255;
        Fs[k * TILE_B + r] = features[(size_t)(b0 + r) * DFEAT + k];
    }

    // ---- top-k init: warp w owns rows 2w, 2w+1 ----
    #pragma unroll
    for (int rr = 0; rr < 2; rr++) {
        int r = 2 * warp + rr;
        if (lane < GRAPHK)      { vals[r*52 + lane]      = NEG_INF; labs[r*52 + lane]      = 0xFFFFFFFFu; }
        if (lane + 32 < GRAPHK) { vals[r*52 + lane + 32] = NEG_INF; labs[r*52 + lane + 32] = 0xFFFFFFFFu; }
    }
    float minv[2] = {NEG_INF, NEG_INF};
    int   minpos[2] = {0, 0};

    const int NCHUNK = (Nh + TILE_N - 1) / TILE_N;
    const int TOT    = NCHUNK * NKST;

    // compute geometry: lane tile 8 rows x 4 cols
    const int wr    = warp >> 3;                  // row group 0/1 (16 rows each)
    const int cg    = warp & 7;                   // col group (64 cols)
    const int rh    = lane >> 4;                  // 0/1 (8-row half)
    const int rbase = 16 * wr + 8 * rh;
    const int c0    = cg * 64 + (lane & 15);      // cols c0 + 16*cc, cc=0..3
    const int swc   = (c0 >> 1) & 3;              // a-unit swizzle key

    // ---- staging: 4 x 16B cp.async per thread per stage ----
    auto issue_stage = [&](int ss, int buf) {
        const int kb = (ss & (NKST - 1)) * KSTAGE;
        const int n0 = n_begin + (ss >> 4) * TILE_N;
        const uint32_t base = As_bytes + (uint32_t)buf * (TILE_N * KSTAGE * 4);
        #pragma unroll
        for (int j = 0; j < 4; j++) {
            int id = tx + NTHREADS * j;      // 0..2047
            int n  = id >> 2;                // 0..511
            int u  = id & 3;                 // k-quad
            int gn = n0 + n;
            int ok = (gn < n_end);
            const float* src = anchor + (size_t)(ok ? gn : 0) * DFEAT + kb + 4 * u;
            uint32_t dst = base + (uint32_t)(n * 64 + 16 * ((u ^ (n >> 1)) & 3));
            cpasync16(dst, src, ok ? 16 : 0);
        }
        cp_commit();
    };

    issue_stage(0, 0);
    issue_stage(1, 1);

    ull acc[4][4];
    #pragma unroll
    for (int p = 0; p < 4; p++)
        #pragma unroll
        for (int c = 0; c < 4; c++) acc[p][c] = 0ull;

    int buf = 0;
    for (int ss = 0; ss < TOT; ss++) {
        cp_wait<1>();       // my copies for stage ss complete
        __syncthreads();    // everyone's copies complete; buf (ss+2)%3 free

        if (ss + 2 < TOT) issue_stage(ss + 2, (buf + 2) % RING);

        // ---- compute: 16 k-steps ----
        const int kg0 = (ss & (NKST - 1)) * KSTAGE;
        const float* A = As + buf * (TILE_N * KSTAGE);
        #pragma unroll
        for (int kq = 0; kq < 4; kq++) {
            // hoist f operand: 4 kk x 8 rows (as 4 f32x2 each)
            ulonglong2 F[4][2];
            const float* fb = Fs + (kg0 + 4 * kq) * TILE_B + rbase;
            #pragma unroll
            for (int kk = 0; kk < 4; kk++) {
                F[kk][0] = *(const ulonglong2*)(fb + kk * TILE_B);
                F[kk][1] = *(const ulonglong2*)(fb + kk * TILE_B + 4);
            }
            const int uo = 4 * ((kq ^ swc) & 3);
            #pragma unroll
            for (int h = 0; h < 2; h++) {
                float4 ax = *(const float4*)(A + (c0 + 32*h)      * KSTAGE + uo);
                float4 ay = *(const float4*)(A + (c0 + 32*h + 16) * KSTAGE + uo);
                #pragma unroll
                for (int kk = 0; kk < 4; kk++) {
                    float sx = (kk==0)?ax.x:(kk==1)?ax.y:(kk==2)?ax.z:ax.w;
                    float sy = (kk==0)?ay.x:(kk==1)?ay.y:(kk==2)?ay.z:ay.w;
                    ull dx = packdup(sx);
                    ull dy = packdup(sy);
                    ull fl0 = F[kk][0].x, fl1 = F[kk][0].y;
                    ull fh0 = F[kk][1].x, fh1 = F[kk][1].y;
                    acc[0][2*h]   = ffma2(fl0, dx, acc[0][2*h]);
                    acc[1][2*h]   = ffma2(fl1, dx, acc[1][2*h]);
                    acc[2][2*h]   = ffma2(fh0, dx, acc[2][2*h]);
                    acc[3][2*h]   = ffma2(fh1, dx, acc[3][2*h]);
                    acc[0][2*h+1] = ffma2(fl0, dy, acc[0][2*h+1]);
                    acc[1][2*h+1] = ffma2(fl1, dy, acc[1][2*h+1]);
                    acc[2][2*h+1] = ffma2(fh0, dy, acc[2][2*h+1]);
                    acc[3][2*h+1] = ffma2(fh1, dy, acc[3][2*h+1]);
                }
            }
        }

        // ---- chunk epilogue every NKST stages ----
        if ((ss & (NKST - 1)) == (NKST - 1)) {
            const int n0 = n_begin + (ss >> 4) * TILE_N;
            #pragma unroll
            for (int p = 0; p < 4; p++) {
                #pragma unroll
                for (int c = 0; c < 4; c++) {
                    float2 v = *(float2*)&acc[p][c];
                    int row0 = rbase + 2 * p;
                    int col  = c0 + 16 * c;
                    stg[row0       * TILE_N + col] = v.x;
                    stg[(row0 + 1) * TILE_N + col] = v.y;
                    acc[p][c] = 0ull;
                }
            }
            __syncthreads();

            int valid = n_end - n0; if (valid > TILE_N) valid = TILE_N;
            #pragma unroll
            for (int rr = 0; rr < 2; rr++) {
                const int r = 2 * warp + rr;
                const float* srow = stg + r * TILE_N;
                float mv = minv[rr]; int mp = minpos[rr];
                for (int base = 0; base < TILE_N; base += 32) {
                    int j = base + lane;
                    float v = srow[j];
                    bool cand = (j < valid) && (v > mv);
                    unsigned m = __ballot_sync(FULLMASK, cand);
                    while (m) {
                        int src = __ffs(m) - 1; m &= m - 1;
                        float vv = __shfl_sync(FULLMASK, v, src);
                        if (vv > mv) {
                            if (lane == 0) {
                                int gidx = n0 + base + src;
                                vals[r*52 + mp] = vv;
                                labs[r*52 + mp] = (unsigned)gidx |
                                                  ((unsigned)anchor_label[gidx] << 16);
                            }
                            __syncwarp();
                            float x = (lane < GRAPHK) ? vals[r*52 + lane] : POS_INF;
                            int   p = lane;
                            if (lane + 32 < GRAPHK) {
                                float x2 = vals[r*52 + lane + 32];
                                if (x2 < x) { x = x2; p = lane + 32; }
                            }
                            #pragma unroll
                            for (int off = 16; off; off >>= 1) {
                                float ox = __shfl_down_sync(FULLMASK, x, off);
                                int   op = __shfl_down_sync(FULLMASK, p, off);
                                if (ox < x) { x = ox; p = op; }
                            }
                            mv = __shfl_sync(FULLMASK, x, 0);
                            mp = __shfl_sync(FULLMASK, p, 0);
                        }
                    }
                }
                minv[rr] = mv; minpos[rr] = mp;
            }
        }
        buf++; if (buf == RING) buf = 0;
    }

    // ---- dump per-half top-k candidates to scratch ----
    #pragma unroll
    for (int rr = 0; rr < 2; rr++) {
        const int r   = 2 * warp + rr;
        const int row = b0 + r;
        if (lane < GRAPHK) {
            g_svals[half][row][lane] = vals[r*52 + lane];
            g_smeta[half][row][lane] = labs[r*52 + lane];
        }
        if (lane + 32 < GRAPHK) {
            g_svals[half][row][lane + 32] = vals[r*52 + lane + 32];
            g_smeta[half][row][lane + 32] = labs[r*52 + lane + 32];
        }
    }
}

// ---- merge: exact top-50 of the 2x50 candidates per row ----
__global__ __launch_bounds__(256, 4)
void knn_sim_merge(const int* __restrict__ labels,
                   float* __restrict__ out, int B)
{
    __shared__ float    mv[8][2 * GRAPHK];
    __shared__ unsigned mm[8][2 * GRAPHK];

    const int lane = threadIdx.x & 31;
    const int w    = threadIdx.x >> 5;
    const int row  = blockIdx.x * 8 + w;
    if (row >= B) return;

    #pragma unroll
    for (int j = 0; j < 4; j++) {
        int c = lane + 32 * j;
        if (c < 2 * GRAPHK) {
            int h = c / GRAPHK, s = c % GRAPHK;
            mv[w][c] = g_svals[h][row][s];
            mm[w][c] = g_smeta[h][row][s];
        }
    }
    __syncwarp();

    const unsigned lbl = (unsigned)labels[row];
    float sum = 0.f; int cnt = 0;
    #pragma unroll
    for (int j = 0; j < 4; j++) {
        int c = lane + 32 * j;
        if (c < 2 * GRAPHK) {
            float    vi = mv[w][c];
            unsigned mi = mm[w][c];
            int rank = 0;
            for (int k = 0; k < 2 * GRAPHK; k++) {
                float    vk = mv[w][k];
                unsigned mk = mm[w][k];
                rank += (vk > vi) || (vk == vi && (mk & 0xFFFFu) < (mi & 0xFFFFu));
            }
            if (rank < GRAPHK) {
                sum += vi;
                cnt += ((mi >> 16) == lbl);
            }
        }
    }
    #pragma unroll
    for (int off = 16; off; off >>= 1) {
        sum += __shfl_down_sync(FULLMASK, sum, off);
        cnt += __shfl_down_sync(FULLMASK, cnt, off);
    }
    if (lane == 0) {
        out[row]     = -(float)cnt * (1.0f / GRAPHK);
        out[B + row] = sum * (1.0f / GRAPHK);
    }
}

extern "C" void kernel_launch(void* const* d_in, const int* in_sizes, int n_in,
                              void* d_out, int out_size)
{
    const float* features     = (const float*)d_in[0];
    const float* anchor       = (const float*)d_in[1];
    const int*   labels       = (const int*)d_in[2];
    // d_in[3] = t_labels (unused)
    const int*   anchor_label = (const int*)d_in[4];
    float* out = (float*)d_out;

    const int B = in_sizes[2];   // 2048
    const int N = in_sizes[4];   // 50000

    cudaFuncSetAttribute(knn_sim_main,
                         cudaFuncAttributeMaxDynamicSharedMemorySize, SMEM_BYTES);

    dim3 grid((B / TILE_B) * 2);   // 64 row-tiles x 2 N-halves = 128 CTAs
    knn_sim_main<<<grid, NTHREADS, SMEM_BYTES>>>(features, anchor, anchor_label, B, N);
    knn_sim_merge<<<(B + 7) / 8, 256>>>(labels, out, B);
}

// round 9
// speedup vs baseline: 1.2931x; 1.2931x over previous
#include <cuda_runtime.h>
#include <cuda_bf16.h>
#include <cstdint>

typedef unsigned long long ull;

#define GRAPHK   50
#define DFEAT    256
#define BROWS    2048
#define NTILES   391                 // ceil(50000/128)
#define NPADR    (NTILES * 128)      // 50048
#define SIMW     NPADR
#define KC       64
#define TILEB    16384               // 128 rows x 64 bf16 x 2B
#define BUFB     (6 * TILEB)         // 3 F splits + 3 A splits
#define SMGEMM   (2 * BUFB)          // 196608 bytes

#define NEG_INF (-3.402823466e38f)
#define POS_INF ( 3.402823466e38f)
#define FULLMASK 0xffffffffu

__device__ __nv_bfloat16 g_A0[(size_t)NPADR * DFEAT];
__device__ __nv_bfloat16 g_A1[(size_t)NPADR * DFEAT];
__device__ __nv_bfloat16 g_A2[(size_t)NPADR * DFEAT];
__device__ __nv_bfloat16 g_F0[(size_t)BROWS * DFEAT];
__device__ __nv_bfloat16 g_F1[(size_t)BROWS * DFEAT];
__device__ __nv_bfloat16 g_F2[(size_t)BROWS * DFEAT];
__device__ float         g_sim[(size_t)BROWS * SIMW];

__device__ __forceinline__ uint32_t smem_u32(const void* p) {
    uint32_t a;
    asm("{ .reg .u64 t; cvta.to.shared.u64 t, %1; cvt.u32.u64 %0, t; }" : "=r"(a) : "l"(p));
    return a;
}
__device__ __forceinline__ void cpasync16(uint32_t dst, const void* src) {
    asm volatile("cp.async.cg.shared.global [%0], [%1], 16;" :: "r"(dst), "l"(src));
}
__device__ __forceinline__ void cp_commit() { asm volatile("cp.async.commit_group;" ::: "memory"); }
template <int M> __device__ __forceinline__ void cp_wait() {
    asm volatile("cp.async.wait_group %0;" :: "n"(M) : "memory");
}

#define LDSM4(r, addr) \
    asm volatile("ldmatrix.sync.aligned.m8n8.x4.shared.b16 {%0,%1,%2,%3}, [%4];" \
        : "=r"((r)[0]), "=r"((r)[1]), "=r"((r)[2]), "=r"((r)[3]) : "r"(addr))

#define MMA16816(d, a, b0_, b1_) \
    asm volatile("mma.sync.aligned.m16n8k16.row.col.f32.bf16.bf16.f32 " \
        "{%0,%1,%2,%3}, {%4,%5,%6,%7}, {%8,%9}, {%0,%1,%2,%3};" \
        : "+f"((d)[0]), "+f"((d)[1]), "+f"((d)[2]), "+f"((d)[3]) \
        : "r"((a)[0]), "r"((a)[1]), "r"((a)[2]), "r"((a)[3]), "r"(b0_), "r"(b1_))

// ---- kernel 1: fp32 -> 3-way bf16 split (zero-pad past valid) ----
__global__ void ksplit(const float* __restrict__ src, long valid, long total,
                       __nv_bfloat16* __restrict__ h, __nv_bfloat16* __restrict__ m,
                       __nv_bfloat16* __restrict__ l)
{
    long i  = (long)blockIdx.x * blockDim.x + threadIdx.x;
    long st = (long)gridDim.x * blockDim.x;
    for (; i < total; i += st) {
        float x = (i < valid) ? src[i] : 0.0f;
        __nv_bfloat16 hh = __float2bfloat16(x);
        float r1 = x - __bfloat162float(hh);
        __nv_bfloat16 mm = __float2bfloat16(r1);
        float r2 = r1 - __bfloat162float(mm);
        h[i] = hh; m[i] = mm; l[i] = __float2bfloat16(r2);
    }
}

// ---- kernel 2: HMMA split-GEMM -> g_sim ----
__global__ __launch_bounds__(256, 1)
void kgemm()
{
    extern __shared__ char smc[];
    const uint32_t sb = smem_u32(smc);

    const int tx     = threadIdx.x;
    const int lane   = tx & 31;
    const int warp   = tx >> 5;          // 0..7
    const int warp_m = warp & 1;         // 64-row group
    const int warp_n = warp >> 1;        // 32-col group
    const int mtile  = blockIdx.x & 15;
    const int ntile  = blockIdx.x >> 4;
    const int m0     = mtile * 128;
    const int n0     = ntile * 128;

    const __nv_bfloat16* gF[3] = {g_F0, g_F1, g_F2};
    const __nv_bfloat16* gA[3] = {g_A0, g_A1, g_A2};
    const int pa[6] = {0, 0, 1, 0, 2, 1};
    const int pb[6] = {0, 1, 0, 2, 0, 1};

    // ldmatrix per-lane geometry
    const int l7 = lane & 7;
    const int qa = (lane >> 3) & 1;      // q bit0
    const int qb = (lane >> 4) & 1;      // q bit1
    uint32_t rA[4], rB[2];
    #pragma unroll
    for (int mf = 0; mf < 4; mf++) rA[mf] = warp_m * 64 + mf * 16 + qa * 8 + l7;
    #pragma unroll
    for (int ng = 0; ng < 2; ng++) rB[ng] = warp_n * 32 + ng * 16 + qb * 8 + l7;

    auto stage = [&](int kc, int buf) {
        const uint32_t base = sb + (uint32_t)buf * BUFB;
        const int kc0 = kc * KC;
        #pragma unroll
        for (int j = 0; j < 24; j++) {
            int gid = tx + 256 * j;       // 0..6143
            int t   = gid >> 10;          // tile 0..5
            int u   = gid & 1023;
            int row = u >> 3, ku = u & 7;
            const __nv_bfloat16* sp;
            size_t grow;
            if (t < 3) { sp = gF[t];     grow = (size_t)(m0 + row); }
            else       { sp = gA[t - 3]; grow = (size_t)(n0 + row); }
            const char* src = (const char*)(sp + grow * DFEAT + kc0 + 8 * ku);
            uint32_t dst = base + (uint32_t)(t * TILEB + row * 128 + 16 * (ku ^ (row & 7)));
            cpasync16(dst, src);
        }
        cp_commit();
    };

    float acc[4][4][4];
    #pragma unroll
    for (int i = 0; i < 4; i++)
        #pragma unroll
        for (int j = 0; j < 4; j++)
            #pragma unroll
            for (int c = 0; c < 4; c++) acc[i][j][c] = 0.f;

    stage(0, 0);

    for (int kc = 0; kc < 4; kc++) {
        const int buf = kc & 1;
        if (kc + 1 < 4) { stage(kc + 1, buf ^ 1); cp_wait<1>(); }
        else            { cp_wait<0>(); }
        __syncthreads();

        const uint32_t bb = sb + (uint32_t)buf * BUFB;
        #pragma unroll
        for (int p = 0; p < 6; p++) {
            const uint32_t at = bb + pa[p] * TILEB;
            const uint32_t bt = bb + (3 + pb[p]) * TILEB;
            #pragma unroll
            for (int kf = 0; kf < 4; kf++) {
                uint32_t a[4][4], b[2][4];
                #pragma unroll
                for (int mf = 0; mf < 4; mf++)
                    LDSM4(a[mf], at + rA[mf] * 128 + 16 * ((unsigned)((2*kf + qb) ^ (rA[mf] & 7))));
                #pragma unroll
                for (int ng = 0; ng < 2; ng++)
                    LDSM4(b[ng], bt + rB[ng] * 128 + 16 * ((unsigned)((2*kf + qa) ^ (rB[ng] & 7))));
                #pragma unroll
                for (int mf = 0; mf < 4; mf++) {
                    #pragma unroll
                    for (int nf = 0; nf < 4; nf++)
                        MMA16816(acc[mf][nf], a[mf], b[nf >> 1][2 * (nf & 1)], b[nf >> 1][2 * (nf & 1) + 1]);
                }
            }
        }
        __syncthreads();   // buf free before it is restaged
    }

    // ---- epilogue: c-frag -> g_sim ----
    const int crow  = lane >> 2;
    const int ccol2 = (lane & 3) * 2;
    #pragma unroll
    for (int mf = 0; mf < 4; mf++) {
        #pragma unroll
        for (int nf = 0; nf < 4; nf++) {
            size_t gr = (size_t)(m0 + warp_m * 64 + mf * 16 + crow);
            size_t gc = (size_t)(n0 + warp_n * 32 + nf * 8 + ccol2);
            float* d = g_sim + gr * SIMW + gc;
            *(float2*)d              = make_float2(acc[mf][nf][0], acc[mf][nf][1]);
            *(float2*)(d + 8 * SIMW) = make_float2(acc[mf][nf][2], acc[mf][nf][3]);
        }
    }
}

// ---- kernel 3: full-row top-k + finalize ----
__global__ __launch_bounds__(256, 4)
void ktopk(const int* __restrict__ labels, const int* __restrict__ anchor_label,
           float* __restrict__ out, int B, int N)
{
    __shared__ float vals[8][GRAPHK];
    __shared__ int   labs[8][GRAPHK];
    const int lane = threadIdx.x & 31;
    const int w    = threadIdx.x >> 5;
    const int row  = blockIdx.x * 8 + w;
    if (row >= B) return;

    if (lane < GRAPHK)      { vals[w][lane]      = NEG_INF; labs[w][lane]      = -1; }
    if (lane + 32 < GRAPHK) { vals[w][lane + 32] = NEG_INF; labs[w][lane + 32] = -1; }
    __syncwarp();

    float mv = NEG_INF; int mp = 0;
    const float* srow = g_sim + (size_t)row * SIMW;
    for (int base = 0; base < N; base += 128) {
        float v[4];
        #pragma unroll
        for (int q = 0; q < 4; q++) {
            int j = base + 32 * q + lane;
            v[q] = (j < N) ? srow[j] : NEG_INF;
        }
        #pragma unroll
        for (int q = 0; q < 4; q++) {
            unsigned mask = __ballot_sync(FULLMASK, v[q] > mv);
            while (mask) {
                int src = __ffs(mask) - 1; mask &= mask - 1;
                float vv = __shfl_sync(FULLMASK, v[q], src);
                if (vv > mv) {
                    if (lane == 0) {
                        vals[w][mp] = vv;
                        labs[w][mp] = anchor_label[base + 32 * q + src];
                    }
                    __syncwarp();
                    float x = (lane < GRAPHK) ? vals[w][lane] : POS_INF;
                    int p = lane;
                    if (lane + 32 < GRAPHK) {
                        float x2 = vals[w][lane + 32];
                        if (x2 < x) { x = x2; p = lane + 32; }
                    }
                    #pragma unroll
                    for (int off = 16; off; off >>= 1) {
                        float ox = __shfl_down_sync(FULLMASK, x, off);
                        int   op = __shfl_down_sync(FULLMASK, p, off);
                        if (ox < x) { x = ox; p = op; }
                    }
                    mv = __shfl_sync(FULLMASK, x, 0);
                    mp = __shfl_sync(FULLMASK, p, 0);
                }
            }
        }
    }
    const int lbl = labels[row];
    float sv = 0.f; int cnt = 0;
    if (lane < GRAPHK)      { sv  = vals[w][lane];      cnt  = (labs[w][lane]      == lbl); }
    if (lane + 32 < GRAPHK) { sv += vals[w][lane + 32]; cnt += (labs[w][lane + 32] == lbl); }
    #pragma unroll
    for (int off = 16; off; off >>= 1) {
        sv  += __shfl_down_sync(FULLMASK, sv, off);
        cnt += __shfl_down_sync(FULLMASK, cnt, off);
    }
    if (lane == 0) {
        out[row]     = -(float)cnt * (1.0f / GRAPHK);
        out[B + row] = sv * (1.0f / GRAPHK);
    }
}

extern "C" void kernel_launch(void* const* d_in, const int* in_sizes, int n_in,
                              void* d_out, int out_size)
{
    const float* features     = (const float*)d_in[0];
    const float* anchor       = (const float*)d_in[1];
    const int*   labels       = (const int*)d_in[2];
    // d_in[3] = t_labels (unused)
    const int*   anchor_label = (const int*)d_in[4];
    float* out = (float*)d_out;
    const int B = in_sizes[2];   // 2048
    const int N = in_sizes[4];   // 50000

    __nv_bfloat16 *a0, *a1, *a2, *f0, *f1, *f2;
    cudaGetSymbolAddress((void**)&a0, g_A0);
    cudaGetSymbolAddress((void**)&a1, g_A1);
    cudaGetSymbolAddress((void**)&a2, g_A2);
    cudaGetSymbolAddress((void**)&f0, g_F0);
    cudaGetSymbolAddress((void**)&f1, g_F1);
    cudaGetSymbolAddress((void**)&f2, g_F2);

    ksplit<<<592, 256>>>(anchor,   (long)N * DFEAT, (long)NPADR * DFEAT, a0, a1, a2);
    ksplit<<<148, 256>>>(features, (long)B * DFEAT, (long)B * DFEAT,     f0, f1, f2);

    cudaFuncSetAttribute(kgemm, cudaFuncAttributeMaxDynamicSharedMemorySize, SMGEMM);
    kgemm<<<NTILES * 16, 256, SMGEMM>>>();

    ktopk<<<(B + 7) / 8, 256>>>(labels, anchor_label, out, B, N);
}